// round 15
// baseline (speedup 1.0000x reference)
#include <cuda_runtime.h>
#include <math.h>

#define NQ 10
#define DIM 1024
#define NPAIR 45
#define NG 55
#define TT 128
#define FS 133          // padded feat row stride
#define NTH 256
#define NL 3
#define NA 3
#define NE 2            // batch elements per CTA
#define PI_F 3.14159265358979323846f

// Upper-triangle (i<j) pair indices, row-major: 45 pairs.
__constant__ int c_PI[NPAIR] = {0,0,0,0,0,0,0,0,0, 1,1,1,1,1,1,1,1, 2,2,2,2,2,2,2,
                                3,3,3,3,3,3, 4,4,4,4,4, 5,5,5,5, 6,6,6, 7,7, 8};
__constant__ int c_PJ[NPAIR] = {1,2,3,4,5,6,7,8,9, 2,3,4,5,6,7,8,9, 3,4,5,6,7,8,9,
                                4,5,6,7,8,9, 5,6,7,8,9, 6,7,8,9, 7,8,9, 8,9, 9};
// Gram tasks: all (i<=j) pairs incl diagonal, row-major: 55.
__constant__ int c_TI[NG] = {0,0,0,0,0,0,0,0,0,0, 1,1,1,1,1,1,1,1,1, 2,2,2,2,2,2,2,2,
                             3,3,3,3,3,3,3, 4,4,4,4,4,4, 5,5,5,5,5, 6,6,6,6, 7,7,7, 8,8, 9};
__constant__ int c_TJ[NG] = {0,1,2,3,4,5,6,7,8,9, 1,2,3,4,5,6,7,8,9, 2,3,4,5,6,7,8,9,
                             3,4,5,6,7,8,9, 4,5,6,7,8,9, 5,6,7,8,9, 6,7,8,9, 7,8,9, 8,9, 9};
// Offset of (i,i) within the 55-list.
__constant__ int c_OFF[NQ] = {0,10,19,27,34,40,45,49,52,54};
// Per-warp task quarters over the 55 Gram tasks.
__constant__ int c_LO4[5] = {0,14,28,42,55};

__device__ __forceinline__ int idx45(int i, int j) {
    return i * 9 - ((i * (i + 1)) >> 1) + j - 1;
}

__device__ __forceinline__ float2 cxmul(float2 a, float2 b) {
    return make_float2(a.x*b.x - a.y*b.y, a.x*b.y + a.y*b.x);
}
__device__ __forceinline__ float2 cxadd(float2 a, float2 b) {
    return make_float2(a.x + b.x, a.y + b.y);
}

// SU(2) butterfly; U=(u00.x,u00.y,u01.x,u01.y); row2 = (-conj(u01), conj(u00)).
__device__ __forceinline__ void bf_su2(float4 U,
                                       float& r0, float& i0, float& r1, float& i1) {
    float n0r =  U.x*r0 - U.y*i0 + U.z*r1 - U.w*i1;
    float n0i =  U.x*i0 + U.y*r0 + U.z*i1 + U.w*r1;
    float n1r = -U.z*r0 - U.w*i0 + U.x*r1 + U.y*i1;
    float n1i = -U.z*i0 + U.w*r0 + U.x*i1 - U.y*r1;
    r0 = n0r; i0 = n0i; r1 = n1r; i1 = n1i;
}

// Shuffle butterfly on lane bit k; SU(2), bit-dependent signs folded once.
__device__ __forceinline__ void lane_gate_su2(float4 U, bool bit, int k,
                                              float aR[4], float aI[4]) {
    float sy = bit ? -U.y : U.y;
    float sx = bit ? -U.z : U.z;
    #pragma unroll
    for (int r = 0; r < 4; r++) {
        float pr = __shfl_xor_sync(0xffffffffu, aR[r], 1 << k);
        float pi = __shfl_xor_sync(0xffffffffu, aI[r], 1 << k);
        float nr = U.x*aR[r] - sy*aI[r] + sx*pr - U.w*pi;
        float ni = U.x*aI[r] + sy*aR[r] + sx*pi + U.w*pr;
        aR[r] = nr; aI[r] = ni;
    }
}

// View-B map: swap amp bits [9:7] <-> slot bits [2:0].
__device__ __forceinline__ int sigma(int j) {
    return (j & 0x078) | ((j & 7) << 7) | (j >> 7);
}
__device__ __forceinline__ int ADDR(int s) { return ((s & 3) << 8) | (s >> 2); }
__device__ __forceinline__ int swz(int a) {
    return a ^ ((a >> 5) & 0xF) ^ ((a >> 1) & 8) ^ ((a >> 2) & 1);
}

__global__ __launch_bounds__(NTH, 4)
void qh_kernel(const float* __restrict__ c_kt,
               const float* __restrict__ dc_kt,
               const float* __restrict__ vqc,
               const float* __restrict__ wproj,
               const float* __restrict__ bproj,
               const float* __restrict__ lalpha,
               float* __restrict__ out)
{
    // Pool: 4 exchange buffers (8KB each). feat[NE][NQ*FS] (10640B) aliases the
    // first half — all feat reads complete (phase 2) before any buf write (hot loop).
    __shared__ __align__(16) char pool[4 * DIM * 8];
    float*  feat = (float*)pool;
    float2* bufA = (float2*)pool;
    float2* bufB = (float2*)(pool + DIM * 8);
    float2* bufC = (float2*)(pool + 2 * DIM * 8);
    float2* bufD = (float2*)(pool + 3 * DIM * 8);

    __shared__ int lutA[NL][32], lutB[NL][32];
    __shared__ float G[NE][NG];
    __shared__ float Ssum[NE][NQ];
    __shared__ float Jp[NE][NPAIR];
    __shared__ float cth[NE][NQ], sth[NE][NQ], phh[NE][NQ];
    __shared__ float thetaS[NE][NQ], phiS[NE][NQ];
    __shared__ float4 gm2[NE][NL][NQ];    // SU(2) gate per element (folds theta/phi)
    __shared__ float wsh[NA][NQ];
    __shared__ float wred[NE][8][4];
    // nibble tables per element: h1 = tid[7:4], h2 = tid[3:0]
    __shared__ float T1mag[NE][16], T1ph[NE][16], T1J[NE][16], TA1[NE][16], TB1[NE][16];
    __shared__ float T2mag[NE][16], T2ph[NE][16], T2J[NE][16], TA2[NE][16], TB2[NE][16];
    __shared__ float Rrow[NE][4][16];
    __shared__ float W1[NA][16], W2[NA][16];

    const int bx   = blockIdx.x;
    const int tid  = threadIdx.x;
    const int warp = tid >> 5;
    const int lane = tid & 31;

    // ---- phase 1: stage inputs (both elements) + permutation LUTs ----
    for (int i = tid; i < NE * NQ * TT; i += NTH) {
        int e = i / (NQ * TT), r = i - e * (NQ * TT);
        int t = r / NQ, k = r - t * NQ;
        size_t g = (size_t)(2 * bx + e) * (NQ * TT) + r;
        feat[e * (NQ * FS) + k * FS + t] = fmaf(0.5f, dc_kt[g], c_kt[g]);
    }
    if (tid < NE * NQ) {
        int e = tid / NQ, q = tid - e * NQ;
        size_t base = (size_t)(2 * bx + e) * (NQ * TT) + (TT - 1) * NQ + q;
        thetaS[e][q] = c_kt[base];
        phiS[e][q]   = dc_kt[base];
    }
    if (tid >= 224 && tid < 224 + NA * NQ) {
        int i = tid - 224;
        wsh[i / NQ][i - (i / NQ) * NQ] = wproj[i];
    }
    if (tid >= 32 && tid < 224) {
        int k6 = tid - 32;                 // 0..191
        int l = k6 / 64, k = k6 & 63;
        int idx = (k < 32) ? k : ((k - 32) << 5);
        const int rng = l + 1;
        #pragma unroll
        for (int q = NQ - 1; q >= 0; q--) {
            int tgt = q + rng; if (tgt >= NQ) tgt -= NQ;
            if ((idx >> (NQ - 1 - q)) & 1) idx ^= 1 << (NQ - 1 - tgt);
        }
        int p = swz(ADDR(sigma(idx)));
        if (k < 32) lutA[l][k] = p; else lutB[l][k - 32] = p;
    }
    __syncthreads();

    // ---- phase 2: Gram dots + row sums; warps 0-3 -> elem0, 4-7 -> elem1 ----
    {
        const int e = warp >> 2, we = warp & 3;
        const float* fe = feat + e * (NQ * FS);
        const int lo = c_LO4[we], hi = c_LO4[we + 1];
        int cur_i = -1;
        float vi0=0.f, vi1=0.f, vi2=0.f, vi3=0.f;
        for (int tk = lo; tk < hi; tk++) {
            int i = c_TI[tk], j = c_TJ[tk];
            if (i != cur_i) {
                cur_i = i;
                const float* fi = fe + i * FS + lane;
                vi0 = fi[0]; vi1 = fi[32]; vi2 = fi[64]; vi3 = fi[96];
            }
            float s;
            if (j == i) {
                s = vi0*vi0 + vi1*vi1 + vi2*vi2 + vi3*vi3;
                float ss = vi0 + vi1 + vi2 + vi3;
                #pragma unroll
                for (int o = 16; o; o >>= 1) ss += __shfl_xor_sync(0xffffffffu, ss, o);
                if (lane == 0) Ssum[e][i] = ss;
            } else {
                const float* fj = fe + j * FS + lane;
                s = vi0*fj[0] + vi1*fj[32] + vi2*fj[64] + vi3*fj[96];
            }
            #pragma unroll
            for (int o = 16; o; o >>= 1) s += __shfl_xor_sync(0xffffffffu, s, o);
            if (lane == 0) G[e][tk] = s;
        }
    }
    __syncthreads();

    // ---- phase 3 (parallel sub-jobs) ----
    if (tid < NPAIR || (tid >= 64 && tid < 64 + NPAIR)) {
        int e = (tid >= 64) ? 1 : 0;
        int p = tid - e * 64;
        int i = c_PI[p], j = c_PJ[p];
        float Si = Ssum[e][i], Sj = Ssum[e][j];
        const float invT = 1.f / TT, invT1 = 1.f / (TT - 1);
        float vi = (G[e][c_OFF[i]] - Si * Si * invT) * invT1;
        float vj = (G[e][c_OFF[j]] - Sj * Sj * invT) * invT1;
        float si = fmaxf(sqrtf(vi), 1e-8f);
        float sj = fmaxf(sqrtf(vj), 1e-8f);
        float num = (G[e][c_OFF[i] + (j - i)] - Si * Sj * invT) * invT1;
        float rho = num / (si * sj);
        Jp[e][p] = __tanhf(rho * __expf(lalpha[0]));
    } else if (tid >= 120 && tid < 120 + NE * NQ) {
        int k = tid - 120;
        int e = k / NQ, q = k - e * NQ;
        float sq, cq;
        __sincosf(0.5f * thetaS[e][q], &sq, &cq);
        cth[e][q] = cq; sth[e][q] = sq;
        phh[e][q] = 0.5f * phiS[e][q];
    } else if (tid >= 160 && tid < 160 + NE * NL * NQ) {
        int idx = tid - 160;
        int e = idx / (NL * NQ), rem = idx - e * (NL * NQ);
        int l = rem / NQ, q = rem - l * NQ;
        float a  = vqc[rem * 3 + 0];
        float bb = vqc[rem * 3 + 1];
        float c  = vqc[rem * 3 + 2];
        float sb2, cb2; __sincosf(0.5f * bb, &sb2, &cb2);
        float apc = 0.5f * (a + c), amc = 0.5f * (a - c);
        float capc, sapc, camc, samc;
        __sincosf(apc, &sapc, &capc);
        __sincosf(amc, &samc, &camc);
        float2 u00 = make_float2( capc * cb2, -sapc * cb2);
        float2 u01 = make_float2(-camc * sb2, -samc * sb2);
        if (l != 0) {
            float thq = 0.25f * thetaS[e][q], phq = 0.25f * phiS[e][q];
            float st, ct; __sincosf(thq, &st, &ct);
            float sp, cp; __sincosf(phq, &sp, &cp);
            float2 A00 = make_float2( cp * ct, -sp * ct);
            float2 A01 = make_float2(-cp * st,  sp * st);
            float2 A10 = make_float2(-A01.x,  A01.y);
            float2 A11 = make_float2( A00.x, -A00.y);
            float2 v00 = cxadd(cxmul(u00, A00), cxmul(u01, A10));
            float2 v01 = cxadd(cxmul(u00, A01), cxmul(u01, A11));
            u00 = v00; u01 = v01;
        }
        gm2[e][l][q] = make_float4(u00.x, u00.y, u01.x, u01.y);
    }
    __syncthreads();

    // ---- phase 3.5: nibble tables (per element) + shared W tables ----
    if (tid < 64) {
        int e = tid >> 5, k = tid & 31;
        if (k < 16) {
            int h = k;
            float m = 1.f, p = 0.f, jj = 0.f, aa = 0.f, bv = 0.f;
            #pragma unroll
            for (int q = 0; q < 4; q++) {
                bool bit = (h >> (3 - q)) & 1;
                m *= bit ? sth[e][q] : cth[e][q];
                p += bit ? phh[e][q] : -phh[e][q];
                float ja = Jp[e][idx45(q, 8)], jb = Jp[e][idx45(q, 9)];
                aa += bit ? ja : -ja;
                bv += bit ? jb : -jb;
            }
            #pragma unroll
            for (int i = 0; i < 3; i++)
                #pragma unroll
                for (int j2 = i + 1; j2 < 4; j2++) {
                    bool si = (h >> (3 - i)) & 1, sj = (h >> (3 - j2)) & 1;
                    float v = Jp[e][idx45(i, j2)];
                    jj += (si ^ sj) ? v : -v;
                }
            T1mag[e][h] = m; T1ph[e][h] = p; T1J[e][h] = jj; TA1[e][h] = aa; TB1[e][h] = bv;
        } else {
            int h = k - 16;
            float m = 1.f, p = 0.f, jj = 0.f, aa = 0.f, bv = 0.f;
            #pragma unroll
            for (int q = 4; q < 8; q++) {
                bool bit = (h >> (7 - q)) & 1;
                m *= bit ? sth[e][q] : cth[e][q];
                p += bit ? phh[e][q] : -phh[e][q];
                float ja = Jp[e][idx45(q, 8)], jb = Jp[e][idx45(q, 9)];
                aa += bit ? ja : -ja;
                bv += bit ? jb : -jb;
            }
            #pragma unroll
            for (int i = 4; i < 7; i++)
                #pragma unroll
                for (int j2 = i + 1; j2 < 8; j2++) {
                    bool si = (h >> (7 - i)) & 1, sj = (h >> (7 - j2)) & 1;
                    float v = Jp[e][idx45(i, j2)];
                    jj += (si ^ sj) ? v : -v;
                }
            T2mag[e][h] = m; T2ph[e][h] = p; T2J[e][h] = jj; TA2[e][h] = aa; TB2[e][h] = bv;
        }
    } else if (tid < 192) {
        int e = (tid - 64) >> 6, ee = (tid - 64) & 63;
        int i = ee >> 4, h2 = ee & 15;
        float r = 0.f;
        #pragma unroll
        for (int j2 = 4; j2 < 8; j2++) {
            bool bit = (h2 >> (7 - j2)) & 1;
            float v = Jp[e][idx45(i, j2)];
            r += bit ? v : -v;
        }
        Rrow[e][i][h2] = r;
    } else {
        int ent = tid - 192;   // 0..63, entries 0..95: do ent and ent+64 (ent<32)
        #pragma unroll
        for (int pass = 0; pass < 2; pass++) {
            int en = ent + pass * 64;
            if (en < 96) {
                int half = en / 48, rem = en - half * 48;
                int a = rem >> 4, h = rem & 15;
                float g = 0.f;
                #pragma unroll
                for (int k = 0; k < 4; k++) {
                    int q = half * 4 + k;
                    bool bit = (h >> (3 - k)) & 1;
                    float w = wsh[a][q];
                    g += bit ? -w : w;
                }
                if (half == 0) W1[a][h] = g; else W2[a][h] = g;
            }
        }
    }
    __syncthreads();

    // ===================== state in registers (2 elements) =====================
    float aR[NE][4], aI[NE][4];
    {
        const int h1 = tid >> 4, h2 = tid & 15;
        #pragma unroll
        for (int e = 0; e < NE; e++) {
            float magHi = T1mag[e][h1] * T2mag[e][h2];
            float phHi  = T1ph[e][h1] + T2ph[e][h2];
            float base  = T1J[e][h1] + T2J[e][h2];
            #pragma unroll
            for (int i = 0; i < 4; i++) {
                bool ti = (h1 >> (3 - i)) & 1;
                float rv = Rrow[e][i][h2];
                base += ti ? -rv : rv;
            }
            float A  = TA1[e][h1] + TA2[e][h2];
            float Bv = TB1[e][h1] + TB2[e][h2];
            float C = Jp[e][44];
            float c8 = cth[e][8], s8 = sth[e][8], c9 = cth[e][9], s9 = sth[e][9];
            float p8 = phh[e][8], p9 = phh[e][9];
            #pragma unroll
            for (int r = 0; r < 4; r++) {
                bool b8 = (r >> 1) & 1, b9 = r & 1;
                float mag = magHi * (b8 ? s8 : c8) * (b9 ? s9 : c9);
                float ph  = phHi + (b8 ? p8 : -p8) + (b9 ? p9 : -p9);
                float aJ  = base + (b8 ? -A : A) + (b9 ? -Bv : Bv) + ((b8 ^ b9) ? C : -C);
                ph = fmaf(0.5f * PI_F, aJ, ph);
                float sp, cp; __sincosf(ph, &sp, &cp);
                aR[e][r] = mag * cp; aI[e][r] = mag * sp;
            }
        }
    }

    const int ftid = swz(tid);
    int pbase = (((tid >> 5) & 3) << 8) | (tid & 0x1E) | ((tid & 1) << 7) | (tid >> 7);
    const int fpb = swz(pbase);
    const int cstS[4] = {0x000, 0x108, 0x200, 0x308};
    const int cstG[4] = {0x00, 0x21, 0x42, 0x63};
    const int laIdxBase = (tid & 7) << 2;
    const int lbIdx = tid >> 3;

    #pragma unroll
    for (int l = 0; l < NL; l++) {
        // register gates q=9, q=8 (both elements; independent chains)
        #pragma unroll
        for (int e = 0; e < NE; e++) {
            float4 U = gm2[e][l][9];
            bf_su2(U, aR[e][0], aI[e][0], aR[e][1], aI[e][1]);
            bf_su2(U, aR[e][2], aI[e][2], aR[e][3], aI[e][3]);
            float4 V = gm2[e][l][8];
            bf_su2(V, aR[e][0], aI[e][0], aR[e][2], aI[e][2]);
            bf_su2(V, aR[e][1], aI[e][1], aR[e][3], aI[e][3]);
        }
        // lane gates q=7..3
        #pragma unroll
        for (int q = 7; q >= 3; q--) {
            const int k = 7 - q;
            const bool bit = (lane >> k) & 1;
            lane_gate_su2(gm2[0][l][q], bit, k, aR[0], aI[0]);
            lane_gate_su2(gm2[1][l][q], bit, k, aR[1], aI[1]);
        }

        // exchange to view B: elem0 -> bufA, elem1 -> bufC
        #pragma unroll
        for (int r = 0; r < 4; r++) {
            bufA[ftid ^ cstS[r]] = make_float2(aR[0][r], aI[0][r]);
            bufC[ftid ^ cstS[r]] = make_float2(aR[1][r], aI[1][r]);
        }
        __syncthreads();
        #pragma unroll
        for (int r = 0; r < 4; r++) {
            float2 v0 = bufA[fpb ^ cstG[r]];
            float2 v1 = bufC[fpb ^ cstG[r]];
            aR[0][r] = v0.x; aI[0][r] = v0.y;
            aR[1][r] = v1.x; aI[1][r] = v1.y;
        }

        // view-B gates: q=2, q=1 (register), q=0 (lane bit0)
        #pragma unroll
        for (int e = 0; e < NE; e++) {
            float4 U = gm2[e][l][2];
            bf_su2(U, aR[e][0], aI[e][0], aR[e][1], aI[e][1]);
            bf_su2(U, aR[e][2], aI[e][2], aR[e][3], aI[e][3]);
            float4 V = gm2[e][l][1];
            bf_su2(V, aR[e][0], aI[e][0], aR[e][2], aI[e][2]);
            bf_su2(V, aR[e][1], aI[e][1], aR[e][3], aI[e][3]);
        }
        {
            const bool bit = lane & 1;
            lane_gate_su2(gm2[0][l][0], bit, 0, aR[0], aI[0]);
            lane_gate_su2(gm2[1][l][0], bit, 0, aR[1], aI[1]);
        }

        // exchange back + composed-CNOT perm (LUT loaded once, reused for both)
        #pragma unroll
        for (int r = 0; r < 4; r++) {
            bufB[ftid ^ cstS[r]] = make_float2(aR[0][r], aI[0][r]);
            bufD[ftid ^ cstS[r]] = make_float2(aR[1][r], aI[1][r]);
        }
        __syncthreads();
        {
            int mb = lutB[l][lbIdx];
            #pragma unroll
            for (int r = 0; r < 4; r++) {
                int ad = mb ^ lutA[l][laIdxBase | r];
                float2 v0 = bufB[ad];
                float2 v1 = bufD[ad];
                aR[0][r] = v0.x; aI[0][r] = v0.y;
                aR[1][r] = v1.x; aI[1][r] = v1.y;
            }
        }
    }

    // ---- epilogue (both elements) ----
    {
        const int h1 = tid >> 4, h2 = tid & 15;
        #pragma unroll
        for (int e = 0; e < NE; e++) {
            float g0Hi = W1[0][h1] + W2[0][h2];
            float g1Hi = W1[1][h1] + W2[1][h2];
            float g2Hi = W1[2][h1] + W2[2][h2];
            float w08 = wsh[0][8], w09 = wsh[0][9];
            float w18 = wsh[1][8], w19 = wsh[1][9];
            float w28 = wsh[2][8], w29 = wsh[2][9];
            float acc0 = 0.f, acc1 = 0.f, acc2 = 0.f;
            #pragma unroll
            for (int r = 0; r < 4; r++) {
                bool b8 = (r >> 1) & 1, b9 = r & 1;
                float pr = aR[e][r]*aR[e][r] + aI[e][r]*aI[e][r];
                acc0 = fmaf(pr, g0Hi + (b8 ? -w08 : w08) + (b9 ? -w09 : w09), acc0);
                acc1 = fmaf(pr, g1Hi + (b8 ? -w18 : w18) + (b9 ? -w19 : w19), acc1);
                acc2 = fmaf(pr, g2Hi + (b8 ? -w28 : w28) + (b9 ? -w29 : w29), acc2);
            }
            #pragma unroll
            for (int o = 16; o; o >>= 1) {
                acc0 += __shfl_xor_sync(0xffffffffu, acc0, o);
                acc1 += __shfl_xor_sync(0xffffffffu, acc1, o);
                acc2 += __shfl_xor_sync(0xffffffffu, acc2, o);
            }
            if (lane == 0) {
                wred[e][warp][0] = acc0; wred[e][warp][1] = acc1; wred[e][warp][2] = acc2;
            }
        }
    }
    __syncthreads();
    if (tid < NA) {
        float s = bproj[tid];
        #pragma unroll
        for (int w = 0; w < 8; w++) s += wred[0][w][tid];
        out[(2 * bx) * NA + tid] = s;
    } else if (tid >= 32 && tid < 32 + NA) {
        int a = tid - 32;
        float s = bproj[a];
        #pragma unroll
        for (int w = 0; w < 8; w++) s += wred[1][w][a];
        out[(2 * bx + 1) * NA + a] = s;
    }
}

extern "C" void kernel_launch(void* const* d_in, const int* in_sizes, int n_in,
                              void* d_out, int out_size) {
    const float* c_kt   = (const float*)d_in[0];
    const float* dc_kt  = (const float*)d_in[1];
    const float* vqc    = (const float*)d_in[2];
    const float* wproj  = (const float*)d_in[3];
    const float* bproj  = (const float*)d_in[4];
    const float* lalpha = (const float*)d_in[5];
    int B = in_sizes[0] / (NQ * TT);
    qh_kernel<<<B / NE, NTH>>>(c_kt, dc_kt, vqc, wproj, bproj, lalpha, (float*)d_out);
}